// round 1
// baseline (speedup 1.0000x reference)
#include <cuda_runtime.h>
#include <math.h>

#define B_    32
#define CIN_  256
#define H_    28
#define W_    28
#define HW_   784
#define COUT_ 256
#define KEXP_ 4
#define HID_  64
#define RTOT_ 2304   // CIN*9

// Scratch (allocation-free rule: __device__ globals)
__device__ float g_prob[B_ * KEXP_ * COUT_];              // [b][k][o]
__device__ float g_aggw[(size_t)B_ * COUT_ * RTOT_];      // [b][o][ci*9+t]  (75.5 MB)

// ---------------------------------------------------------------------------
// Kernel 1: routing.  One block per sample, 256 threads.
// pooled = mean(x, HW); h = relu(pooled @ fc1^T); y = h @ fc2^T + b;
// prob = softmax(y / sqrt(64), over K)
// ---------------------------------------------------------------------------
__global__ void routing_kernel(const float* __restrict__ x,
                               const float* __restrict__ fc1_w,
                               const float* __restrict__ fc2_w,
                               const float* __restrict__ fc2_b) {
    int b    = blockIdx.x;
    int tid  = threadIdx.x;
    int lane = tid & 31;
    int warp = tid >> 5;

    __shared__ float pooled[CIN_];
    __shared__ float hs[HID_];

    // ---- pooling: one warp per channel (coalesced within warp) ----
    for (int c = warp; c < CIN_; c += 8) {
        const float* xp = x + ((size_t)b * CIN_ + c) * HW_;
        float s = 0.f;
        for (int i = lane; i < HW_; i += 32) s += xp[i];
        #pragma unroll
        for (int off = 16; off; off >>= 1) s += __shfl_xor_sync(0xffffffffu, s, off);
        if (lane == 0) pooled[c] = s * (1.0f / 784.0f);
    }
    __syncthreads();

    // ---- fc1 + relu (64 outputs, one per thread) ----
    if (tid < HID_) {
        const float* wr = fc1_w + (size_t)tid * CIN_;
        float acc = 0.f;
        #pragma unroll 8
        for (int c = 0; c < CIN_; ++c) acc += pooled[c] * wr[c];
        hs[tid] = fmaxf(acc, 0.f);
    }
    __syncthreads();

    // ---- fc2 + softmax over K, one output-channel per thread ----
    int o = tid;  // 0..255
    float y[KEXP_];
    #pragma unroll
    for (int k = 0; k < KEXP_; ++k) {
        int m = k * COUT_ + o;
        const float* wr = fc2_w + (size_t)m * HID_;
        float acc = fc2_b[m];
        #pragma unroll 8
        for (int j = 0; j < HID_; ++j) acc += hs[j] * wr[j];
        y[k] = acc * 0.125f;   // / sqrt(HIDDEN=64)
    }
    float mx = fmaxf(fmaxf(y[0], y[1]), fmaxf(y[2], y[3]));
    float e[KEXP_], se = 0.f;
    #pragma unroll
    for (int k = 0; k < KEXP_; ++k) { e[k] = expf(y[k] - mx); se += e[k]; }
    float inv = 1.0f / se;
    #pragma unroll
    for (int k = 0; k < KEXP_; ++k)
        g_prob[((size_t)b * KEXP_ + k) * COUT_ + o] = e[k] * inv;
}

// ---------------------------------------------------------------------------
// Kernel 2: aggregate per-sample conv weights.
// agg[b,o,r] = sum_k prob[b,k,o] * weight[k,o,r],  r in [0,2304)
// grid (o=256, b=32), 256 threads
// ---------------------------------------------------------------------------
__global__ void aggw_kernel(const float* __restrict__ weight) {
    int o   = blockIdx.x;
    int b   = blockIdx.y;
    int tid = threadIdx.x;

    float p0 = g_prob[((size_t)b * KEXP_ + 0) * COUT_ + o];
    float p1 = g_prob[((size_t)b * KEXP_ + 1) * COUT_ + o];
    float p2 = g_prob[((size_t)b * KEXP_ + 2) * COUT_ + o];
    float p3 = g_prob[((size_t)b * KEXP_ + 3) * COUT_ + o];

    const float* w0 = weight + ((size_t)(0 * COUT_ + o)) * RTOT_;
    const float* w1 = weight + ((size_t)(1 * COUT_ + o)) * RTOT_;
    const float* w2 = weight + ((size_t)(2 * COUT_ + o)) * RTOT_;
    const float* w3 = weight + ((size_t)(3 * COUT_ + o)) * RTOT_;
    float* dst = g_aggw + ((size_t)b * COUT_ + o) * RTOT_;

    for (int j = tid; j < RTOT_; j += 256)
        dst[j] = p0 * w0[j] + p1 * w1[j] + p2 * w2[j] + p3 * w3[j];
}

// ---------------------------------------------------------------------------
// Kernel 3: per-sample 3x3 conv (pad 1) with aggregated weights.
// Block tile: 64 out channels x (4 rows x 28 cols).  CI chunk = 16.
// Thread micro-tile: 4 outs x 7 pixels (28 fp32 accumulators).
// grid (rowtile=7, otile=4, b=32), 256 threads.
// smem: x halo tile 16x6x30 (11.5 KB) + w tile 64x145 padded (37.1 KB)
// ---------------------------------------------------------------------------
#define CI_T 16

__global__ __launch_bounds__(256, 2)
void conv_kernel(const float* __restrict__ x, float* __restrict__ out) {
    __shared__ float xs[CI_T * 180];   // [ci][row 0..5][col 0..29]  (halo +-1)
    __shared__ float ws[64 * 145];     // [o][ci*9+t], padded stride 145

    int b  = blockIdx.z;
    int o0 = blockIdx.y * 64;
    int r0 = blockIdx.x * 4;
    int tid = threadIdx.x;
    int tx = tid & 15;            // pixel group
    int ty = tid >> 4;            // out group (16 groups x 4 outs)
    int prow = tx >> 2;           // output row within tile: 0..3
    int pcol = (tx & 3) * 7;      // output col base: 0,7,14,21

    float acc[4][7];
    #pragma unroll
    for (int oo = 0; oo < 4; ++oo)
        #pragma unroll
        for (int j = 0; j < 7; ++j) acc[oo][j] = 0.f;

    const float* wsrc_base = g_aggw + ((size_t)b * COUT_ + o0) * RTOT_;

    for (int ci0 = 0; ci0 < CIN_; ci0 += CI_T) {
        // ---- load x halo tile (coalesced along cols) ----
        for (int idx = tid; idx < CI_T * 180; idx += 256) {
            int ci  = idx / 180;
            int rem = idx - ci * 180;
            int rr  = rem / 30;
            int cc  = rem - rr * 30;
            int grow = r0 + rr - 1;
            int gcol = cc - 1;
            float v = 0.f;
            if ((unsigned)grow < 28u && (unsigned)gcol < 28u)
                v = x[(((size_t)b * CIN_ + ci0 + ci) * 28 + grow) * 28 + gcol];
            xs[idx] = v;
        }
        // ---- load w tile (64 outs x 144 taps for this ci chunk) ----
        const float* wsrc = wsrc_base + ci0 * 9;
        for (int idx = tid; idx < 64 * 144; idx += 256) {
            int o = idx / 144;
            int r = idx - o * 144;
            ws[o * 145 + r] = wsrc[(size_t)o * RTOT_ + r];
        }
        __syncthreads();

        // ---- compute ----
        #pragma unroll 2
        for (int ci = 0; ci < CI_T; ++ci) {
            const float* xci = xs + ci * 180;
            #pragma unroll
            for (int kh = 0; kh < 3; ++kh) {
                float xv[9];
                const float* xp = xci + (prow + kh) * 30 + pcol;
                #pragma unroll
                for (int j = 0; j < 9; ++j) xv[j] = xp[j];
                #pragma unroll
                for (int kw = 0; kw < 3; ++kw) {
                    int wi = ci * 9 + kh * 3 + kw;
                    #pragma unroll
                    for (int oo = 0; oo < 4; ++oo) {
                        float wv = ws[(ty * 4 + oo) * 145 + wi];
                        #pragma unroll
                        for (int j = 0; j < 7; ++j)
                            acc[oo][j] = fmaf(wv, xv[j + kw], acc[oo][j]);
                    }
                }
            }
        }
        __syncthreads();
    }

    // ---- write out ----
    #pragma unroll
    for (int oo = 0; oo < 4; ++oo) {
        float* op = out + (((size_t)b * COUT_ + o0 + ty * 4 + oo) * 28 + (r0 + prow)) * 28 + pcol;
        #pragma unroll
        for (int j = 0; j < 7; ++j) op[j] = acc[oo][j];
    }
}

// ---------------------------------------------------------------------------
extern "C" void kernel_launch(void* const* d_in, const int* in_sizes, int n_in,
                              void* d_out, int out_size) {
    const float* x     = (const float*)d_in[0];   // [32,256,28,28]
    const float* fc1_w = (const float*)d_in[1];   // [64,256]
    const float* fc2_w = (const float*)d_in[2];   // [1024,64]
    const float* fc2_b = (const float*)d_in[3];   // [1024]
    const float* wexp  = (const float*)d_in[4];   // [4,256,256,3,3]
    float* out = (float*)d_out;                   // [32,256,28,28]

    routing_kernel<<<B_, 256>>>(x, fc1_w, fc2_w, fc2_b);
    aggw_kernel<<<dim3(COUT_, B_), 256>>>(wexp);
    conv_kernel<<<dim3(7, 4, B_), 256>>>(x, out);
}

// round 2
// speedup vs baseline: 1.1052x; 1.1052x over previous
#include <cuda_runtime.h>
#include <math.h>

#define B_    32
#define CIN_  256
#define H_    28
#define W_    28
#define HW_   784
#define COUT_ 256
#define KEXP_ 4
#define HID_  64
#define RTOT_ 2304   // CIN*9

typedef unsigned long long u64;

// Scratch (allocation-free rule: __device__ globals)
__device__ float g_pooled[B_ * CIN_];
__device__ float g_prob[B_ * KEXP_ * COUT_];              // [b][k][o]
__device__ float g_aggw[(size_t)B_ * COUT_ * RTOT_];      // [b][o][ci*9+t]  (75.5 MB)

// ---------------------------------------------------------------------------
// Kernel 0: pooling.  One warp per (b, channel).  1024 blocks x 256 thr.
// ---------------------------------------------------------------------------
__global__ void pool_kernel(const float* __restrict__ x) {
    int gw   = blockIdx.x * 8 + (threadIdx.x >> 5);   // 0..8191
    int lane = threadIdx.x & 31;
    const float4* xp = (const float4*)(x + (size_t)gw * HW_);
    float s = 0.f;
    for (int i = lane; i < HW_ / 4; i += 32) {
        float4 v = xp[i];
        s += (v.x + v.y) + (v.z + v.w);
    }
    #pragma unroll
    for (int off = 16; off; off >>= 1) s += __shfl_xor_sync(0xffffffffu, s, off);
    if (lane == 0) g_pooled[gw] = s * (1.0f / 784.0f);
}

// ---------------------------------------------------------------------------
// Kernel 1: routing (fc1 + fc2 + softmax).  One block per sample, 256 thr.
// ---------------------------------------------------------------------------
__global__ void routing_kernel(const float* __restrict__ fc1_w,
                               const float* __restrict__ fc2_w,
                               const float* __restrict__ fc2_b) {
    int b   = blockIdx.x;
    int tid = threadIdx.x;

    __shared__ float pooled[CIN_];
    __shared__ float hs[HID_];

    pooled[tid] = g_pooled[b * CIN_ + tid];
    __syncthreads();

    if (tid < HID_) {
        const float* wr = fc1_w + (size_t)tid * CIN_;
        float acc = 0.f;
        #pragma unroll 8
        for (int c = 0; c < CIN_; ++c) acc += pooled[c] * wr[c];
        hs[tid] = fmaxf(acc, 0.f);
    }
    __syncthreads();

    int o = tid;  // 0..255
    float y[KEXP_];
    #pragma unroll
    for (int k = 0; k < KEXP_; ++k) {
        int m = k * COUT_ + o;
        const float* wr = fc2_w + (size_t)m * HID_;
        float acc = fc2_b[m];
        #pragma unroll 8
        for (int j = 0; j < HID_; ++j) acc += hs[j] * wr[j];
        y[k] = acc * 0.125f;   // / sqrt(HIDDEN=64)
    }
    float mx = fmaxf(fmaxf(y[0], y[1]), fmaxf(y[2], y[3]));
    float e[KEXP_], se = 0.f;
    #pragma unroll
    for (int k = 0; k < KEXP_; ++k) { e[k] = expf(y[k] - mx); se += e[k]; }
    float inv = 1.0f / se;
    #pragma unroll
    for (int k = 0; k < KEXP_; ++k)
        g_prob[((size_t)b * KEXP_ + k) * COUT_ + o] = e[k] * inv;
}

// ---------------------------------------------------------------------------
// Kernel 2: aggregate per-sample conv weights (float4 vectorized).
// agg[b,o,r] = sum_k prob[b,k,o] * weight[k,o,r]
// ---------------------------------------------------------------------------
__global__ void aggw_kernel(const float* __restrict__ weight) {
    int o   = blockIdx.x;
    int b   = blockIdx.y;
    int tid = threadIdx.x;

    float p0 = g_prob[((size_t)b * KEXP_ + 0) * COUT_ + o];
    float p1 = g_prob[((size_t)b * KEXP_ + 1) * COUT_ + o];
    float p2 = g_prob[((size_t)b * KEXP_ + 2) * COUT_ + o];
    float p3 = g_prob[((size_t)b * KEXP_ + 3) * COUT_ + o];

    const float4* w0 = (const float4*)(weight + ((size_t)(0 * COUT_ + o)) * RTOT_);
    const float4* w1 = (const float4*)(weight + ((size_t)(1 * COUT_ + o)) * RTOT_);
    const float4* w2 = (const float4*)(weight + ((size_t)(2 * COUT_ + o)) * RTOT_);
    const float4* w3 = (const float4*)(weight + ((size_t)(3 * COUT_ + o)) * RTOT_);
    float4* dst = (float4*)(g_aggw + ((size_t)b * COUT_ + o) * RTOT_);

    for (int j = tid; j < RTOT_ / 4; j += 256) {
        float4 a = w0[j], c = w1[j], d = w2[j], f = w3[j];
        float4 r;
        r.x = p0 * a.x + p1 * c.x + p2 * d.x + p3 * f.x;
        r.y = p0 * a.y + p1 * c.y + p2 * d.y + p3 * f.y;
        r.z = p0 * a.z + p1 * c.z + p2 * d.z + p3 * f.z;
        r.w = p0 * a.w + p1 * c.w + p2 * d.w + p3 * f.w;
        dst[j] = r;
    }
}

// ---------------------------------------------------------------------------
// Kernel 3: per-sample 3x3 conv with packed f32x2 FMA.
// Block tile: 64 outs x (4 rows x 28 cols).  CI chunk 16.
// Thread micro-tile: 2 out-PAIRS x 7 pixels (14 f32x2 accumulators).
// Weights stored in smem as interleaved pairs -> single LDS.64 per pair.
// ---------------------------------------------------------------------------
#define CI_T 16

__global__ __launch_bounds__(256, 2)
void conv_kernel(const float* __restrict__ x, float* __restrict__ out) {
    __shared__ float xs[CI_T * 180];      // [ci][row 0..5][col 0..29]
    __shared__ u64   ws2[32 * 145];       // [out-pair][tap] packed (w_even, w_odd)

    int b  = blockIdx.z;
    int o0 = blockIdx.y * 64;
    int r0 = blockIdx.x * 4;
    int tid = threadIdx.x;
    int tx = tid & 15;
    int ty = tid >> 4;            // 16 groups x 4 outs (= 2 pairs)
    int prow = tx >> 2;
    int pcol = (tx & 3) * 7;

    u64 acc2[2][7];
    #pragma unroll
    for (int p = 0; p < 2; ++p)
        #pragma unroll
        for (int j = 0; j < 7; ++j) acc2[p][j] = 0ull;

    const float* wsrc_base = g_aggw + ((size_t)b * COUT_ + o0) * RTOT_;
    float* ws2f = (float*)ws2;

    for (int ci0 = 0; ci0 < CIN_; ci0 += CI_T) {
        // ---- load x halo tile ----
        for (int idx = tid; idx < CI_T * 180; idx += 256) {
            int ci  = idx / 180;
            int rem = idx - ci * 180;
            int rr  = rem / 30;
            int cc  = rem - rr * 30;
            int grow = r0 + rr - 1;
            int gcol = cc - 1;
            float v = 0.f;
            if ((unsigned)grow < 28u && (unsigned)gcol < 28u)
                v = x[(((size_t)b * CIN_ + ci0 + ci) * 28 + grow) * 28 + gcol];
            xs[idx] = v;
        }
        // ---- load w tile, interleaved as out-pairs ----
        const float* wsrc = wsrc_base + ci0 * 9;
        for (int idx = tid; idx < 64 * 144; idx += 256) {
            int o = idx / 144;
            int r = idx - o * 144;
            ws2f[(o >> 1) * 290 + r * 2 + (o & 1)] = wsrc[(size_t)o * RTOT_ + r];
        }
        __syncthreads();

        // ---- compute ----
        #pragma unroll 2
        for (int ci = 0; ci < CI_T; ++ci) {
            const float* xci = xs + ci * 180;
            #pragma unroll
            for (int kh = 0; kh < 3; ++kh) {
                const float* xp = xci + (prow + kh) * 30 + pcol;
                float xv[9];
                u64   xd[9];
                #pragma unroll
                for (int j = 0; j < 9; ++j) {
                    xv[j] = xp[j];
                    asm("mov.b64 %0, {%1, %1};" : "=l"(xd[j]) : "f"(xv[j]));
                }
                #pragma unroll
                for (int kw = 0; kw < 3; ++kw) {
                    int wi = ci * 9 + kh * 3 + kw;
                    #pragma unroll
                    for (int p = 0; p < 2; ++p) {
                        u64 wp = ws2[(ty * 2 + p) * 145 + wi];
                        #pragma unroll
                        for (int j = 0; j < 7; ++j)
                            asm("fma.rn.f32x2 %0, %1, %2, %0;"
                                : "+l"(acc2[p][j]) : "l"(wp), "l"(xd[j + kw]));
                    }
                }
            }
        }
        __syncthreads();
    }

    // ---- write out (unpack pairs) ----
    #pragma unroll
    for (int p = 0; p < 2; ++p) {
        int oe = o0 + ty * 4 + 2 * p;      // even channel of pair
        float* ope = out + (((size_t)b * COUT_ + oe)     * 28 + (r0 + prow)) * 28 + pcol;
        float* opo = out + (((size_t)b * COUT_ + oe + 1) * 28 + (r0 + prow)) * 28 + pcol;
        #pragma unroll
        for (int j = 0; j < 7; ++j) {
            ope[j] = __uint_as_float((unsigned)(acc2[p][j] & 0xffffffffull));
            opo[j] = __uint_as_float((unsigned)(acc2[p][j] >> 32));
        }
    }
}

// ---------------------------------------------------------------------------
extern "C" void kernel_launch(void* const* d_in, const int* in_sizes, int n_in,
                              void* d_out, int out_size) {
    const float* x     = (const float*)d_in[0];   // [32,256,28,28]
    const float* fc1_w = (const float*)d_in[1];   // [64,256]
    const float* fc2_w = (const float*)d_in[2];   // [1024,64]
    const float* fc2_b = (const float*)d_in[3];   // [1024]
    const float* wexp  = (const float*)d_in[4];   // [4,256,256,3,3]
    float* out = (float*)d_out;                   // [32,256,28,28]

    pool_kernel<<<B_ * CIN_ / 8, 256>>>(x);
    routing_kernel<<<B_, 256>>>(fc1_w, fc2_w, fc2_b);
    aggw_kernel<<<dim3(COUT_, B_), 256>>>(wexp);
    conv_kernel<<<dim3(7, 4, B_), 256>>>(x, out);
}

// round 9
// speedup vs baseline: 1.3192x; 1.1937x over previous
#include <cuda_runtime.h>
#include <cuda_bf16.h>
#include <stdint.h>

#define B_    32
#define CIN_  256
#define HW_   784
#define COUT_ 256

// ===========================================================================
// PTX helpers (arch-generic only: ldmatrix + mma.sync, valid on sm_103)
// ===========================================================================
__device__ __forceinline__ uint32_t smem_to_u32(const void* p) {
    uint32_t a;
    asm("{ .reg .u64 t; cvta.to.shared.u64 t, %1; cvt.u32.u64 %0, t; }" : "=r"(a) : "l"(p));
    return a;
}
#define STS128(r0, r1, r2, r3, smem_addr) \
    asm volatile("st.shared.v4.b32 [%0], {%1, %2, %3, %4};" \
        :: "r"(smem_addr), "r"(r0), "r"(r1), "r"(r2), "r"(r3) : "memory")
#define STS64(smem_addr, r0, r1) \
    asm volatile("st.shared.v2.b32 [%0], {%1, %2};" \
        :: "r"(smem_addr), "r"(r0), "r"(r1) : "memory")
#define LDSM_X4(r0, r1, r2, r3, addr) \
    asm volatile("ldmatrix.sync.aligned.m8n8.x4.shared.b16 {%0,%1,%2,%3}, [%4];" \
        : "=r"(r0), "=r"(r1), "=r"(r2), "=r"(r3) : "r"(addr))
#define LDSM_X2(r0, r1, addr) \
    asm volatile("ldmatrix.sync.aligned.m8n8.x2.shared.b16 {%0,%1}, [%2];" \
        : "=r"(r0), "=r"(r1) : "r"(addr))
#define MMA_BF16(d, a, bgg) \
    asm volatile("mma.sync.aligned.m16n8k16.row.col.f32.bf16.bf16.f32 " \
        "{%0,%1,%2,%3}, {%4,%5,%6,%7}, {%8,%9}, {%0,%1,%2,%3};" \
        : "+f"((d)[0]), "+f"((d)[1]), "+f"((d)[2]), "+f"((d)[3]) \
        : "r"((a)[0]), "r"((a)[1]), "r"((a)[2]), "r"((a)[3]), \
          "r"((bgg)[0]), "r"((bgg)[1]))

// ===========================================================================
// Scratch (__device__ globals; allocation-free rule)
// ===========================================================================
__device__ float    g_pooled[B_ * CIN_];
__device__ float    g_prob[B_ * 4 * COUT_];                         // [b][k][o]
__device__ uint32_t g_aggw_split[(size_t)B_ * COUT_ * 9 * CIN_];    // [b][o][tap][ci] packed (hi<<16|lo)

__device__ __forceinline__ uint32_t pack_split(float v) {
    __nv_bfloat16 h = __float2bfloat16(v);
    float rem = v - __bfloat162float(h);
    __nv_bfloat16 l = __float2bfloat16(rem);
    return ((uint32_t)__bfloat16_as_ushort(h) << 16) | (uint32_t)__bfloat16_as_ushort(l);
}

// ---------------------------------------------------------------------------
// Kernel 0: pooling.  One warp per (b, channel).
// ---------------------------------------------------------------------------
__global__ void pool_kernel(const float* __restrict__ x) {
    int gw   = blockIdx.x * 8 + (threadIdx.x >> 5);
    int lane = threadIdx.x & 31;
    const float4* xp = (const float4*)(x + (size_t)gw * HW_);
    float s = 0.f;
    for (int i = lane; i < HW_ / 4; i += 32) {
        float4 v = xp[i];
        s += (v.x + v.y) + (v.z + v.w);
    }
    #pragma unroll
    for (int off = 16; off; off >>= 1) s += __shfl_xor_sync(0xffffffffu, s, off);
    if (lane == 0) g_pooled[gw] = s * (1.0f / 784.0f);
}

// ---------------------------------------------------------------------------
// Kernel 1: routing (fc1 + fc2 + softmax).
// ---------------------------------------------------------------------------
__global__ void routing_kernel(const float* __restrict__ fc1_w,
                               const float* __restrict__ fc2_w,
                               const float* __restrict__ fc2_b) {
    int b   = blockIdx.x;
    int tid = threadIdx.x;
    __shared__ float pooled[CIN_];
    __shared__ float hs[64];

    pooled[tid] = g_pooled[b * CIN_ + tid];
    __syncthreads();
    if (tid < 64) {
        const float* wr = fc1_w + (size_t)tid * CIN_;
        float acc = 0.f;
        #pragma unroll 8
        for (int c = 0; c < CIN_; ++c) acc += pooled[c] * wr[c];
        hs[tid] = fmaxf(acc, 0.f);
    }
    __syncthreads();
    int o = tid;
    float y[4];
    #pragma unroll
    for (int k = 0; k < 4; ++k) {
        int m = k * COUT_ + o;
        const float* wr = fc2_w + (size_t)m * 64;
        float acc = fc2_b[m];
        #pragma unroll 8
        for (int j = 0; j < 64; ++j) acc += hs[j] * wr[j];
        y[k] = acc * 0.125f;
    }
    float mx = fmaxf(fmaxf(y[0], y[1]), fmaxf(y[2], y[3]));
    float e[4], se = 0.f;
    #pragma unroll
    for (int k = 0; k < 4; ++k) { e[k] = expf(y[k] - mx); se += e[k]; }
    float inv = 1.0f / se;
    #pragma unroll
    for (int k = 0; k < 4; ++k)
        g_prob[((size_t)b * 4 + k) * COUT_ + o] = e[k] * inv;
}

// ---------------------------------------------------------------------------
// Kernel 2: aggregate + split + transpose weights to [b][o][tap][ci] packed.
// ---------------------------------------------------------------------------
__global__ void aggw_split_kernel(const float* __restrict__ weight) {
    __shared__ uint32_t s[2304];
    int o = blockIdx.x, b = blockIdx.y, tid = threadIdx.x;

    float p0 = g_prob[((size_t)b * 4 + 0) * COUT_ + o];
    float p1 = g_prob[((size_t)b * 4 + 1) * COUT_ + o];
    float p2 = g_prob[((size_t)b * 4 + 2) * COUT_ + o];
    float p3 = g_prob[((size_t)b * 4 + 3) * COUT_ + o];

    const float* w0 = weight + ((size_t)(0 * COUT_ + o)) * 2304;
    const float* w1 = weight + ((size_t)(1 * COUT_ + o)) * 2304;
    const float* w2 = weight + ((size_t)(2 * COUT_ + o)) * 2304;
    const float* w3 = weight + ((size_t)(3 * COUT_ + o)) * 2304;

    for (int j = tid; j < 2304; j += 256)
        s[j] = pack_split(p0 * w0[j] + p1 * w1[j] + p2 * w2[j] + p3 * w3[j]);
    __syncthreads();

    uint32_t* dst = g_aggw_split + ((size_t)b * COUT_ + o) * 2304;
    for (int j = tid; j < 2304; j += 256) {
        int t = j >> 8, ci = j & 255;                 // j = t*256 + ci
        dst[j] = s[ci * 9 + t];                       // conflict-free (stride 9)
    }
}

// ---------------------------------------------------------------------------
// Kernel 3: conv as bf16-split implicit GEMM on mma.sync (HMMA).
// CTA: M=128 outs x N=112 px (4 image rows).  8 warps: 4(M) x 2(N).
// Warp tile: M=32, N=56.  K per stage: 16 ci -> K'=64 (x4 split expansion).
// Stages: 16 ci-chunks x 9 taps = 144.
// Smem rows padded to 144B: ldmatrix 8-row fetch hits disjoint bank quads.
// ---------------------------------------------------------------------------
__global__ __launch_bounds__(256, 2)
void conv_mma_kernel(const float* __restrict__ x, float* __restrict__ out) {
    __shared__ uint32_t slab[16 * 180];                     // packed-split x halo tile
    __shared__ __align__(16) uint16_t As[128 * 72];         // [o][k'] pad-72
    __shared__ __align__(16) uint16_t Bs[112 * 72];         // [px][k'] pad-72

    int tid = threadIdx.x, lane = tid & 31, wid = tid >> 5;
    int b = blockIdx.z, o0 = blockIdx.y * 128, r0 = blockIdx.x * 4;
    int wm = wid & 3, wn = wid >> 2;                        // warp grid 4x2

    uint32_t sA = smem_to_u32(As), sB = smem_to_u32(Bs);

    float d[2][7][4];
    #pragma unroll
    for (int mt = 0; mt < 2; ++mt)
        #pragma unroll
        for (int nt = 0; nt < 7; ++nt)
            #pragma unroll
            for (int j = 0; j < 4; ++j) d[mt][nt][j] = 0.f;

    // precomputed ldmatrix lane addresses (row part varies per tile/kstep)
    int la_row = (lane & 7) + ((lane >> 3) & 1) * 8;        // A: row within 16
    int la_kb  = (lane >> 4) * 8;                           // A: k block
    int lb_row = (lane & 7) + (lane >> 4) * 8;              // B x4: n within 16
    int lb_kb  = ((lane >> 3) & 1) * 8;                     // B x4: k block
    int lb2_row = lane & 7;                                 // B x2 (ignored lanes>=16 ok)
    int lb2_kb  = ((lane >> 3) & 1) * 8;

    for (int ci0 = 0; ci0 < 256; ci0 += 16) {
        // ---- load + split-pack x slab: [16 ci][6 rows][30 cols] ----
        for (int idx = tid; idx < 16 * 180; idx += 256) {
            int ci = idx / 180, rem = idx - ci * 180;
            int rr = rem / 30, ccx = rem - rr * 30;
            int grow = r0 + rr - 1, gcol = ccx - 1;
            float v = 0.f;
            if ((unsigned)grow < 28u && (unsigned)gcol < 28u)
                v = x[(((size_t)(b * 256 + ci0 + ci)) * 28 + grow) * 28 + gcol];
            slab[idx] = pack_split(v);
        }
        __syncthreads();

        for (int t = 0; t < 9; ++t) {
            int dh = t / 3, dw = t % 3;   // slab offsets (already include +1 halo shift)

            // ---- build A: rows = 128 outs, 2 threads/row, expand packed->bf16 ----
            {
                int m = tid >> 1, half = tid & 1;
                const uint4* src = (const uint4*)(g_aggw_split +
                    (((size_t)(b * 256 + o0 + m)) * 9 + t) * 256 + ci0) + half * 2;
                uint32_t dst = sA + (uint32_t)m * 144 + half * 64;
                #pragma unroll
                for (int g = 0; g < 2; ++g) {
                    uint4 w = src[g];
                    STS128(__byte_perm(w.x, w.x, 0x3232), __byte_perm(w.x, w.x, 0x1010),
                           __byte_perm(w.y, w.y, 0x3232), __byte_perm(w.y, w.y, 0x1010),
                           dst + g * 32);
                    STS128(__byte_perm(w.z, w.z, 0x3232), __byte_perm(w.z, w.z, 0x1010),
                           __byte_perm(w.w, w.w, 0x3232), __byte_perm(w.w, w.w, 0x1010),
                           dst + g * 32 + 16);
                }
            }
            // ---- build B: 112 px rows x 16 ci, shifted slab reads ----
            for (int idx = tid; idx < 112 * 16; idx += 256) {
                int n = idx >> 4, ci = idx & 15;
                int rl = n / 28, c = n - rl * 28;
                uint32_t v = slab[ci * 180 + (rl + dh) * 30 + (c + dw)];
                uint32_t h = __byte_perm(v, v, 0x1032);      // (xl<<16)|xh
                STS64(sB + (uint32_t)n * 144 + ci * 8, h, h);
            }
            __syncthreads();

            // ---- consume: 4 k-steps x (2 m-tiles x 7 n-tiles) mma ----
            #pragma unroll
            for (int ks = 0; ks < 4; ++ks) {
                uint32_t a[2][4];
                #pragma unroll
                for (int mt = 0; mt < 2; ++mt) {
                    uint32_t addr = sA + (uint32_t)(wm * 32 + mt * 16 + la_row) * 144
                                       + (ks * 16 + la_kb) * 2;
                    LDSM_X4(a[mt][0], a[mt][1], a[mt][2], a[mt][3], addr);
                }
                uint32_t bb[7][2];
                #pragma unroll
                for (int np = 0; np < 3; ++np) {
                    uint32_t addr = sB + (uint32_t)(wn * 56 + np * 16 + lb_row) * 144
                                       + (ks * 16 + lb_kb) * 2;
                    LDSM_X4(bb[2 * np][0], bb[2 * np][1], bb[2 * np + 1][0], bb[2 * np + 1][1], addr);
                }
                {
                    uint32_t addr = sB + (uint32_t)(wn * 56 + 48 + lb2_row) * 144
                                       + (ks * 16 + lb2_kb) * 2;
                    LDSM_X2(bb[6][0], bb[6][1], addr);
                }
                #pragma unroll
                for (int mt = 0; mt < 2; ++mt)
                    #pragma unroll
                    for (int nt = 0; nt < 7; ++nt)
                        MMA_BF16(d[mt][nt], a[mt], bb[nt]);
            }
            __syncthreads();
        }
    }

    // ---- epilogue: direct STG.64 (px pairs never cross the 28-col boundary) ----
    #pragma unroll
    for (int mt = 0; mt < 2; ++mt) {
        int obase = o0 + wm * 32 + mt * 16 + (lane >> 2);
        #pragma unroll
        for (int nt = 0; nt < 7; ++nt) {
            int px = wn * 56 + nt * 8 + (lane & 3) * 2;
            int rl = px / 28, c = px - rl * 28;
            float2* p0 = (float2*)(out + (((size_t)(b * 256 + obase)) * 28 + r0 + rl) * 28 + c);
            float2* p1 = (float2*)(out + (((size_t)(b * 256 + obase + 8)) * 28 + r0 + rl) * 28 + c);
            *p0 = make_float2(d[mt][nt][0], d[mt][nt][1]);
            *p1 = make_float2(d[mt][nt][2], d[mt][nt][3]);
        }
    }
}

// ---------------------------------------------------------------------------
extern "C" void kernel_launch(void* const* d_in, const int* in_sizes, int n_in,
                              void* d_out, int out_size) {
    const float* x     = (const float*)d_in[0];   // [32,256,28,28]
    const float* fc1_w = (const float*)d_in[1];   // [64,256]
    const float* fc2_w = (const float*)d_in[2];   // [1024,64]
    const float* fc2_b = (const float*)d_in[3];   // [1024]
    const float* wexp  = (const float*)d_in[4];   // [4,256,256,3,3]
    float* out = (float*)d_out;                   // [32,256,28,28]

    pool_kernel<<<B_ * CIN_ / 8, 256>>>(x);
    routing_kernel<<<B_, 256>>>(fc1_w, fc2_w, fc2_b);
    aggw_split_kernel<<<dim3(COUT_, B_), 256>>>(wexp);
    conv_mma_kernel<<<dim3(7, 2, B_), 256>>>(x, out);
}

// round 10
// speedup vs baseline: 1.8279x; 1.3855x over previous
#include <cuda_runtime.h>
#include <cuda_bf16.h>
#include <stdint.h>

#define B_    32
#define CIN_  256
#define HW_   784
#define COUT_ 256

// ===========================================================================
// PTX helpers (arch-generic only: ldmatrix + mma.sync, valid on sm_103)
// ===========================================================================
__device__ __forceinline__ uint32_t smem_to_u32(const void* p) {
    uint32_t a;
    asm("{ .reg .u64 t; cvta.to.shared.u64 t, %1; cvt.u32.u64 %0, t; }" : "=r"(a) : "l"(p));
    return a;
}
#define STS128(r0, r1, r2, r3, smem_addr) \
    asm volatile("st.shared.v4.b32 [%0], {%1, %2, %3, %4};" \
        :: "r"(smem_addr), "r"(r0), "r"(r1), "r"(r2), "r"(r3) : "memory")
#define LDSM_X4(r0, r1, r2, r3, addr) \
    asm volatile("ldmatrix.sync.aligned.m8n8.x4.shared.b16 {%0,%1,%2,%3}, [%4];" \
        : "=r"(r0), "=r"(r1), "=r"(r2), "=r"(r3) : "r"(addr))
#define LDSM_X2(r0, r1, addr) \
    asm volatile("ldmatrix.sync.aligned.m8n8.x2.shared.b16 {%0,%1}, [%2];" \
        : "=r"(r0), "=r"(r1) : "r"(addr))
#define MMA_BF16(d, a, bgg) \
    asm volatile("mma.sync.aligned.m16n8k16.row.col.f32.bf16.bf16.f32 " \
        "{%0,%1,%2,%3}, {%4,%5,%6,%7}, {%8,%9}, {%0,%1,%2,%3};" \
        : "+f"((d)[0]), "+f"((d)[1]), "+f"((d)[2]), "+f"((d)[3]) \
        : "r"((a)[0]), "r"((a)[1]), "r"((a)[2]), "r"((a)[3]), \
          "r"((bgg)[0]), "r"((bgg)[1]))

// ===========================================================================
// Scratch (__device__ globals; allocation-free rule)
// ===========================================================================
__device__ float    g_pooled[B_ * CIN_];
__device__ float    g_prob[B_ * 4 * COUT_];                         // [b][k][o]
__device__ uint32_t g_aggw_split[(size_t)B_ * COUT_ * 9 * CIN_];    // [b][o][tap][ci] packed (hi<<16|lo)

__device__ __forceinline__ uint32_t pack_split(float v) {
    __nv_bfloat16 h = __float2bfloat16(v);
    float rem = v - __bfloat162float(h);
    __nv_bfloat16 l = __float2bfloat16(rem);
    return ((uint32_t)__bfloat16_as_ushort(h) << 16) | (uint32_t)__bfloat16_as_ushort(l);
}

// ---------------------------------------------------------------------------
// Kernel 0: pooling.  One warp per (b, channel).
// ---------------------------------------------------------------------------
__global__ void pool_kernel(const float* __restrict__ x) {
    int gw   = blockIdx.x * 8 + (threadIdx.x >> 5);
    int lane = threadIdx.x & 31;
    const float4* xp = (const float4*)(x + (size_t)gw * HW_);
    float s = 0.f;
    for (int i = lane; i < HW_ / 4; i += 32) {
        float4 v = xp[i];
        s += (v.x + v.y) + (v.z + v.w);
    }
    #pragma unroll
    for (int off = 16; off; off >>= 1) s += __shfl_xor_sync(0xffffffffu, s, off);
    if (lane == 0) g_pooled[gw] = s * (1.0f / 784.0f);
}

// ---------------------------------------------------------------------------
// Kernel 1: routing (fc1 + fc2 + softmax).
// ---------------------------------------------------------------------------
__global__ void routing_kernel(const float* __restrict__ fc1_w,
                               const float* __restrict__ fc2_w,
                               const float* __restrict__ fc2_b) {
    int b   = blockIdx.x;
    int tid = threadIdx.x;
    __shared__ float pooled[CIN_];
    __shared__ float hs[64];

    pooled[tid] = g_pooled[b * CIN_ + tid];
    __syncthreads();
    if (tid < 64) {
        const float* wr = fc1_w + (size_t)tid * CIN_;
        float acc = 0.f;
        #pragma unroll 8
        for (int c = 0; c < CIN_; ++c) acc += pooled[c] * wr[c];
        hs[tid] = fmaxf(acc, 0.f);
    }
    __syncthreads();
    int o = tid;
    float y[4];
    #pragma unroll
    for (int k = 0; k < 4; ++k) {
        int m = k * COUT_ + o;
        const float* wr = fc2_w + (size_t)m * 64;
        float acc = fc2_b[m];
        #pragma unroll 8
        for (int j = 0; j < 64; ++j) acc += hs[j] * wr[j];
        y[k] = acc * 0.125f;
    }
    float mx = fmaxf(fmaxf(y[0], y[1]), fmaxf(y[2], y[3]));
    float e[4], se = 0.f;
    #pragma unroll
    for (int k = 0; k < 4; ++k) { e[k] = expf(y[k] - mx); se += e[k]; }
    float inv = 1.0f / se;
    #pragma unroll
    for (int k = 0; k < 4; ++k)
        g_prob[((size_t)b * 4 + k) * COUT_ + o] = e[k] * inv;
}

// ---------------------------------------------------------------------------
// Kernel 2: aggregate + split + transpose.  Block per o (256 blocks):
// expert rows loaded to smem ONCE, all 32 batches produced from it.
// ---------------------------------------------------------------------------
__global__ void aggw_split_kernel(const float* __restrict__ weight) {
    __shared__ float s[4][2304];   // 36.9 KB
    int o = blockIdx.x, tid = threadIdx.x;

    #pragma unroll
    for (int k = 0; k < 4; ++k) {
        const float* wk = weight + ((size_t)(k * COUT_ + o)) * 2304;
        for (int j = tid; j < 2304; j += 256) s[k][j] = wk[j];
    }
    __syncthreads();

    for (int b = 0; b < B_; ++b) {
        float p0 = g_prob[((size_t)b * 4 + 0) * COUT_ + o];
        float p1 = g_prob[((size_t)b * 4 + 1) * COUT_ + o];
        float p2 = g_prob[((size_t)b * 4 + 2) * COUT_ + o];
        float p3 = g_prob[((size_t)b * 4 + 3) * COUT_ + o];
        uint32_t* dst = g_aggw_split + ((size_t)b * COUT_ + o) * 2304;
        for (int j = tid; j < 2304; j += 256) {
            int t = j >> 8, ci = j & 255;         // output [tap][ci]
            int idx = ci * 9 + t;                 // smem [ci][tap], stride-9 reads
            dst[j] = pack_split(p0 * s[0][idx] + p1 * s[1][idx] +
                                p2 * s[2][idx] + p3 * s[3][idx]);
        }
    }
}

// ---------------------------------------------------------------------------
// Kernel 3: conv as 3-term split-bf16 implicit GEMM on mma.sync.
// CTA: M=128 outs x N=112 px.  8 warps 4(M)x2(N), warp tile 32x56.
// Per tap stage: A=[wh(16ci),wl(16ci)], B=[xh(16ci),xl(16ci)], row stride 80B.
// MMA combos: wh*xh + wl*xh + wh*xl  (wl*xl dropped, ~2^-18 rel).
// Double-buffered A/B staging: ONE barrier per tap.
// ---------------------------------------------------------------------------
#define SLAB_OFF 0          // 16*180 u32 = 11520 B
#define A_OFF    11520      // 2 bufs x 128 rows x 80 B
#define B_OFF    32000      // 2 bufs x 112 rows x 80 B
#define SMEM_SZ  49920

__global__ __launch_bounds__(256, 2)
void conv_mma_kernel(const float* __restrict__ x, float* __restrict__ out) {
    extern __shared__ __align__(16) char dsm[];
    uint32_t* slab = (uint32_t*)(dsm + SLAB_OFF);
    uint32_t sA = smem_to_u32(dsm + A_OFF);
    uint32_t sB = smem_to_u32(dsm + B_OFF);

    int tid = threadIdx.x, lane = tid & 31, wid = tid >> 5;
    int b = blockIdx.z, o0 = blockIdx.y * 128, r0 = blockIdx.x * 4;
    int wm = wid & 3, wn = wid >> 2;

    float d[2][7][4];
    #pragma unroll
    for (int mt = 0; mt < 2; ++mt)
        #pragma unroll
        for (int nt = 0; nt < 7; ++nt)
            #pragma unroll
            for (int j = 0; j < 4; ++j) d[mt][nt][j] = 0.f;

    // ldmatrix lane address components
    int la_row = (lane & 7) + ((lane >> 3) & 1) * 8;   // A rows (16)
    int la_kb  = (lane >> 4) * 16;                     // A k byte offset (0/16)
    int lb_row = (lane & 7) + (lane >> 4) * 8;         // B x4 rows (16)
    int lb_kb  = ((lane >> 3) & 1) * 16;               // B x4 k byte offset
    int lb2_row = lane & 7;                            // B x2 rows (8)
    int lb2_kb  = ((lane >> 3) & 1) * 16;

    // B-build thread mapping (224 active)
    int bn = tid >> 1, bhalf = tid & 1;
    int brl = bn / 28, bc = bn - brl * 28;
    // A-build thread mapping
    int am = tid >> 1, ahalf = tid & 1;

    int stage = 0;
    for (int ci0 = 0; ci0 < 256; ci0 += 16) {
        // ---- load + split-pack x slab: [16 ci][6 rows][30 cols] ----
        for (int idx = tid; idx < 16 * 180; idx += 256) {
            int ci = idx / 180, rem = idx - ci * 180;
            int rr = rem / 30, ccx = rem - rr * 30;
            int grow = r0 + rr - 1, gcol = ccx - 1;
            float v = 0.f;
            if ((unsigned)grow < 28u && (unsigned)gcol < 28u)
                v = x[(((size_t)(b * 256 + ci0 + ci)) * 28 + grow) * 28 + gcol];
            slab[idx] = pack_split(v);
        }
        __syncthreads();

        for (int t = 0; t < 9; ++t) {
            int buf = stage & 1;
            uint32_t sAb = sA + buf * (128 * 80);
            uint32_t sBb = sB + buf * (112 * 80);

            // ---- build A: 2 thr/row; row = [wh x16 | wl x16] ----
            {
                const uint4* src = (const uint4*)(g_aggw_split +
                    (((size_t)(b * 256 + o0 + am)) * 9 + t) * 256 + ci0) + ahalf * 2;
                uint4 w0 = src[0], w1 = src[1];
                uint32_t rb = sAb + (uint32_t)am * 80 + ahalf * 16;
                STS128(__byte_perm(w0.x, w0.y, 0x7632), __byte_perm(w0.z, w0.w, 0x7632),
                       __byte_perm(w1.x, w1.y, 0x7632), __byte_perm(w1.z, w1.w, 0x7632), rb);
                STS128(__byte_perm(w0.x, w0.y, 0x5410), __byte_perm(w0.z, w0.w, 0x5410),
                       __byte_perm(w1.x, w1.y, 0x5410), __byte_perm(w1.z, w1.w, 0x5410), rb + 32);
            }
            // ---- build B: 2 thr/row over 112 rows; row = [xh x16 | xl x16] ----
            if (tid < 224) {
                int dh = t / 3, dw = t % 3;
                const uint32_t* sl = slab + bhalf * 8 * 180 + (brl + dh) * 30 + (bc + dw);
                uint32_t v0 = sl[0], v1 = sl[180], v2 = sl[360], v3 = sl[540];
                uint32_t v4 = sl[720], v5 = sl[900], v6 = sl[1080], v7 = sl[1260];
                uint32_t rb = sBb + (uint32_t)bn * 80 + bhalf * 16;
                STS128(__byte_perm(v0, v1, 0x7632), __byte_perm(v2, v3, 0x7632),
                       __byte_perm(v4, v5, 0x7632), __byte_perm(v6, v7, 0x7632), rb);
                STS128(__byte_perm(v0, v1, 0x5410), __byte_perm(v2, v3, 0x5410),
                       __byte_perm(v4, v5, 0x5410), __byte_perm(v6, v7, 0x5410), rb + 32);
            }
            __syncthreads();

            // ---- consume ----
            uint32_t awh[2][4], awl[2][4], bb[7][2];
            #pragma unroll
            for (int mt = 0; mt < 2; ++mt) {
                uint32_t ra = sAb + (uint32_t)(wm * 32 + mt * 16 + la_row) * 80 + la_kb;
                LDSM_X4(awh[mt][0], awh[mt][1], awh[mt][2], awh[mt][3], ra);
                LDSM_X4(awl[mt][0], awl[mt][1], awl[mt][2], awl[mt][3], ra + 32);
            }
            // B = xh
            #pragma unroll
            for (int np = 0; np < 3; ++np) {
                uint32_t rbm = sBb + (uint32_t)(wn * 56 + np * 16 + lb_row) * 80 + lb_kb;
                LDSM_X4(bb[2*np][0], bb[2*np][1], bb[2*np+1][0], bb[2*np+1][1], rbm);
            }
            LDSM_X2(bb[6][0], bb[6][1],
                    sBb + (uint32_t)(wn * 56 + 48 + lb2_row) * 80 + lb2_kb);
            #pragma unroll
            for (int mt = 0; mt < 2; ++mt)
                #pragma unroll
                for (int nt = 0; nt < 7; ++nt) {
                    MMA_BF16(d[mt][nt], awh[mt], bb[nt]);
                    MMA_BF16(d[mt][nt], awl[mt], bb[nt]);
                }
            // B = xl (reuse regs)
            #pragma unroll
            for (int np = 0; np < 3; ++np) {
                uint32_t rbm = sBb + (uint32_t)(wn * 56 + np * 16 + lb_row) * 80 + 32 + lb_kb;
                LDSM_X4(bb[2*np][0], bb[2*np][1], bb[2*np+1][0], bb[2*np+1][1], rbm);
            }
            LDSM_X2(bb[6][0], bb[6][1],
                    sBb + (uint32_t)(wn * 56 + 48 + lb2_row) * 80 + 32 + lb2_kb);
            #pragma unroll
            for (int mt = 0; mt < 2; ++mt)
                #pragma unroll
                for (int nt = 0; nt < 7; ++nt)
                    MMA_BF16(d[mt][nt], awh[mt], bb[nt]);

            ++stage;
        }
        __syncthreads();   // slab rewrite safety for next chunk
    }

    // ---- epilogue: direct STG.64 ----
    #pragma unroll
    for (int mt = 0; mt < 2; ++mt) {
        int obase = o0 + wm * 32 + mt * 16 + (lane >> 2);
        #pragma unroll
        for (int nt = 0; nt < 7; ++nt) {
            int px = wn * 56 + nt * 8 + (lane & 3) * 2;
            int rl = px / 28, c = px - rl * 28;
            float2* p0 = (float2*)(out + (((size_t)(b * 256 + obase)) * 28 + r0 + rl) * 28 + c);
            float2* p1 = (float2*)(out + (((size_t)(b * 256 + obase + 8)) * 28 + r0 + rl) * 28 + c);
            *p0 = make_float2(d[mt][nt][0], d[mt][nt][1]);
            *p1 = make_float2(d[mt][nt][2], d[mt][nt][3]);
        }
    }
}

// ---------------------------------------------------------------------------
extern "C" void kernel_launch(void* const* d_in, const int* in_sizes, int n_in,
                              void* d_out, int out_size) {
    const float* x     = (const float*)d_in[0];   // [32,256,28,28]
    const float* fc1_w = (const float*)d_in[1];   // [64,256]
    const float* fc2_w = (const float*)d_in[2];   // [1024,64]
    const float* fc2_b = (const float*)d_in[3];   // [1024]
    const float* wexp  = (const float*)d_in[4];   // [4,256,256,3,3]
    float* out = (float*)d_out;                   // [32,256,28,28]

    cudaFuncSetAttribute(conv_mma_kernel, cudaFuncAttributeMaxDynamicSharedMemorySize, SMEM_SZ);

    pool_kernel<<<B_ * CIN_ / 8, 256>>>(x);
    routing_kernel<<<B_, 256>>>(fc1_w, fc2_w, fc2_b);
    aggw_split_kernel<<<COUT_, 256>>>(wexp);
    conv_mma_kernel<<<dim3(7, 2, B_), 256, SMEM_SZ>>>(x, out);
}

// round 12
// speedup vs baseline: 2.2580x; 1.2353x over previous
#include <cuda_runtime.h>
#include <cuda_fp16.h>
#include <stdint.h>

#define B_    32
#define CIN_  256
#define HW_   784
#define COUT_ 256

// ===========================================================================
// PTX helpers (arch-generic: ldmatrix + mma.sync, valid at sm_103 target)
// ===========================================================================
__device__ __forceinline__ uint32_t smem_to_u32(const void* p) {
    uint32_t a;
    asm("{ .reg .u64 t; cvta.to.shared.u64 t, %1; cvt.u32.u64 %0, t; }" : "=r"(a) : "l"(p));
    return a;
}
#define STS128(r0, r1, r2, r3, smem_addr) \
    asm volatile("st.shared.v4.b32 [%0], {%1, %2, %3, %4};" \
        :: "r"(smem_addr), "r"(r0), "r"(r1), "r"(r2), "r"(r3) : "memory")
#define LDSM_X4(r0, r1, r2, r3, addr) \
    asm volatile("ldmatrix.sync.aligned.m8n8.x4.shared.b16 {%0,%1,%2,%3}, [%4];" \
        : "=r"(r0), "=r"(r1), "=r"(r2), "=r"(r3) : "r"(addr))
#define LDSM_X2(r0, r1, addr) \
    asm volatile("ldmatrix.sync.aligned.m8n8.x2.shared.b16 {%0,%1}, [%2];" \
        : "=r"(r0), "=r"(r1) : "r"(addr))
#define MMA_F16(d, a, bgg) \
    asm volatile("mma.sync.aligned.m16n8k16.row.col.f32.f16.f16.f32 " \
        "{%0,%1,%2,%3}, {%4,%5,%6,%7}, {%8,%9}, {%0,%1,%2,%3};" \
        : "+f"((d)[0]), "+f"((d)[1]), "+f"((d)[2]), "+f"((d)[3]) \
        : "r"((a)[0]), "r"((a)[1]), "r"((a)[2]), "r"((a)[3]), \
          "r"((bgg)[0]), "r"((bgg)[1]))

// ===========================================================================
// Scratch (__device__ globals; allocation-free rule)
// ===========================================================================
__device__ float    g_pooled[B_ * CIN_];
__device__ float    g_prob[B_ * 4 * COUT_];                         // [b][k][o]
__device__ uint32_t g_aggw_split[(size_t)B_ * COUT_ * 9 * CIN_];    // [b][o][tap][ci] fp16 packed (hi<<16|lo)

__device__ __forceinline__ uint32_t pack_split_h(float v) {
    __half h = __float2half_rn(v);
    float rem = v - __half2float(h);
    __half l = __float2half_rn(rem);
    return ((uint32_t)__half_as_ushort(h) << 16) | (uint32_t)__half_as_ushort(l);
}

// ---------------------------------------------------------------------------
// Kernel 0: pooling.  One warp per (b, channel).
// ---------------------------------------------------------------------------
__global__ void pool_kernel(const float* __restrict__ x) {
    int gw   = blockIdx.x * 8 + (threadIdx.x >> 5);
    int lane = threadIdx.x & 31;
    const float4* xp = (const float4*)(x + (size_t)gw * HW_);
    float s = 0.f;
    for (int i = lane; i < HW_ / 4; i += 32) {
        float4 v = xp[i];
        s += (v.x + v.y) + (v.z + v.w);
    }
    #pragma unroll
    for (int off = 16; off; off >>= 1) s += __shfl_xor_sync(0xffffffffu, s, off);
    if (lane == 0) g_pooled[gw] = s * (1.0f / 784.0f);
}

// ---------------------------------------------------------------------------
// Kernel 1: routing (fc1 + fc2 + softmax).
// ---------------------------------------------------------------------------
__global__ void routing_kernel(const float* __restrict__ fc1_w,
                               const float* __restrict__ fc2_w,
                               const float* __restrict__ fc2_b) {
    int b   = blockIdx.x;
    int tid = threadIdx.x;
    __shared__ float pooled[CIN_];
    __shared__ float hs[64];

    pooled[tid] = g_pooled[b * CIN_ + tid];
    __syncthreads();
    if (tid < 64) {
        const float* wr = fc1_w + (size_t)tid * CIN_;
        float acc = 0.f;
        #pragma unroll 8
        for (int c = 0; c < CIN_; ++c) acc += pooled[c] * wr[c];
        hs[tid] = fmaxf(acc, 0.f);
    }
    __syncthreads();
    int o = tid;
    float y[4];
    #pragma unroll
    for (int k = 0; k < 4; ++k) {
        int m = k * COUT_ + o;
        const float* wr = fc2_w + (size_t)m * 64;
        float acc = fc2_b[m];
        #pragma unroll 8
        for (int j = 0; j < 64; ++j) acc += hs[j] * wr[j];
        y[k] = acc * 0.125f;
    }
    float mx = fmaxf(fmaxf(y[0], y[1]), fmaxf(y[2], y[3]));
    float e[4], se = 0.f;
    #pragma unroll
    for (int k = 0; k < 4; ++k) { e[k] = expf(y[k] - mx); se += e[k]; }
    float inv = 1.0f / se;
    #pragma unroll
    for (int k = 0; k < 4; ++k)
        g_prob[((size_t)b * 4 + k) * COUT_ + o] = e[k] * inv;
}

// ---------------------------------------------------------------------------
// Kernel 2: aggregate + fp16-split + transpose.  Grid (o=256, bh=2):
// expert rows staged in smem once, 16 batches produced per block.
// ---------------------------------------------------------------------------
__global__ void aggw_split_kernel(const float* __restrict__ weight) {
    __shared__ float s[4][2304];   // 36.9 KB
    int o = blockIdx.x, bh = blockIdx.y, tid = threadIdx.x;

    #pragma unroll
    for (int k = 0; k < 4; ++k) {
        const float* wk = weight + ((size_t)(k * COUT_ + o)) * 2304;
        for (int j = tid; j < 2304; j += 256) s[k][j] = wk[j];
    }
    __syncthreads();

    for (int b = bh * 16; b < bh * 16 + 16; ++b) {
        float p0 = g_prob[((size_t)b * 4 + 0) * COUT_ + o];
        float p1 = g_prob[((size_t)b * 4 + 1) * COUT_ + o];
        float p2 = g_prob[((size_t)b * 4 + 2) * COUT_ + o];
        float p3 = g_prob[((size_t)b * 4 + 3) * COUT_ + o];
        uint32_t* dst = g_aggw_split + ((size_t)b * COUT_ + o) * 2304;
        for (int j = tid; j < 2304; j += 256) {
            int t = j >> 8, ci = j & 255;         // output [tap][ci]
            int idx = ci * 9 + t;                 // smem [ci][tap], stride-9 reads
            dst[j] = pack_split_h(p0 * s[0][idx] + p1 * s[1][idx] +
                                  p2 * s[2][idx] + p3 * s[3][idx]);
        }
    }
}

// ---------------------------------------------------------------------------
// Kernel 3: conv as fp16 2-term split implicit GEMM on mma.sync.
// CTA: M=128 outs x N=112 px.  8 warps 4(M)x2(N), warp tile 32x56.
// B: x tile stored ONCE per ci-chunk as slab_t[spatial][ci] fp16
//    (48B row stride, conflict-free ldmatrix); taps = address offset only.
// A: per tap, [wh x16 | wl x16] fp16 rows, 80B stride, double-buffered.
// MMA: d += wh*xh + wl*xh   (x low bits dropped: ~2.4e-4 rel).
// ---------------------------------------------------------------------------
__global__ __launch_bounds__(256, 2)
void conv_mma_kernel(const float* __restrict__ x, float* __restrict__ out) {
    __shared__ __align__(16) char slabT[180 * 48];       // 8.6 KB
    __shared__ __align__(16) char Abuf[2 * 128 * 80];    // 20.5 KB

    uint32_t sT = smem_to_u32(slabT);
    uint32_t sA = smem_to_u32(Abuf);

    int tid = threadIdx.x, lane = tid & 31, wid = tid >> 5;
    int b = blockIdx.z, o0 = blockIdx.y * 128, r0 = blockIdx.x * 4;
    int wm = wid & 3, wn = wid >> 2;

    float d[2][7][4];
    #pragma unroll
    for (int mt = 0; mt < 2; ++mt)
        #pragma unroll
        for (int nt = 0; nt < 7; ++nt)
            #pragma unroll
            for (int j = 0; j < 4; ++j) d[mt][nt][j] = 0.f;

    // A ldmatrix lane address components
    int la_row = (lane & 7) + ((lane >> 3) & 1) * 8;
    int la_kb  = (lane >> 4) * 16;
    // B ldmatrix lane addresses, precomputed (tap adds a constant offset)
    int lb_row  = (lane & 7) + (lane >> 4) * 8;
    int lb_kb   = ((lane >> 3) & 1) * 16;
    int lb2_row = lane & 7;
    int lb2_kb  = ((lane >> 3) & 1) * 16;
    uint32_t addrB[4];
    #pragma unroll
    for (int np = 0; np < 3; ++np) {
        int n = wn * 56 + np * 16 + lb_row;
        int rl = n / 28, c = n - rl * 28;
        addrB[np] = sT + (uint32_t)(rl * 30 + c) * 48 + lb_kb;
    }
    {
        int n = wn * 56 + 48 + lb2_row;
        int rl = n / 28, c = n - rl * 28;
        addrB[3] = sT + (uint32_t)(rl * 30 + c) * 48 + lb2_kb;
    }

    int am = tid >> 1, ahalf = tid & 1;

    int stage = 0;
    for (int ci0 = 0; ci0 < 256; ci0 += 16) {
        // ---- build slab_t: [s = row*30+col][16 ci] fp16 (hi plane only) ----
        // each thread handles a ci-PAIR so stores are 4B
        for (int idx = tid; idx < 8 * 180; idx += 256) {
            int cp = idx / 180, s = idx - cp * 180;
            int rr = s / 30, cc = s - rr * 30;
            int grow = r0 + rr - 1, gcol = cc - 1;
            float v0 = 0.f, v1 = 0.f;
            if ((unsigned)grow < 28u && (unsigned)gcol < 28u) {
                const float* px = x + (((size_t)(b * 256 + ci0 + 2 * cp)) * 28 + grow) * 28 + gcol;
                v0 = px[0];
                v1 = px[784];
            }
            uint32_t hh = ((uint32_t)__half_as_ushort(__float2half_rn(v1)) << 16)
                        |  (uint32_t)__half_as_ushort(__float2half_rn(v0));
            *(uint32_t*)(slabT + s * 48 + cp * 4) = hh;
        }
        __syncthreads();

        for (int t = 0; t < 9; ++t) {
            int buf = stage & 1;
            uint32_t sAb = sA + buf * (128 * 80);

            // ---- build A: 2 thr/row; row = [wh x16 | wl x16] fp16 ----
            {
                const uint4* src = (const uint4*)(g_aggw_split +
                    (((size_t)(b * 256 + o0 + am)) * 9 + t) * 256 + ci0) + ahalf * 2;
                uint4 w0 = src[0], w1 = src[1];
                uint32_t rb = sAb + (uint32_t)am * 80 + ahalf * 16;
                STS128(__byte_perm(w0.x, w0.y, 0x7632), __byte_perm(w0.z, w0.w, 0x7632),
                       __byte_perm(w1.x, w1.y, 0x7632), __byte_perm(w1.z, w1.w, 0x7632), rb);
                STS128(__byte_perm(w0.x, w0.y, 0x5410), __byte_perm(w0.z, w0.w, 0x5410),
                       __byte_perm(w1.x, w1.y, 0x5410), __byte_perm(w1.z, w1.w, 0x5410), rb + 32);
            }
            __syncthreads();

            // ---- consume ----
            uint32_t dt = (uint32_t)((t / 3) * 30 + (t % 3)) * 48;
            uint32_t awh[2][4], awl[2][4], bb[7][2];
            #pragma unroll
            for (int mt = 0; mt < 2; ++mt) {
                uint32_t ra = sAb + (uint32_t)(wm * 32 + mt * 16 + la_row) * 80 + la_kb;
                LDSM_X4(awh[mt][0], awh[mt][1], awh[mt][2], awh[mt][3], ra);
                LDSM_X4(awl[mt][0], awl[mt][1], awl[mt][2], awl[mt][3], ra + 32);
            }
            #pragma unroll
            for (int np = 0; np < 3; ++np)
                LDSM_X4(bb[2*np][0], bb[2*np][1], bb[2*np+1][0], bb[2*np+1][1],
                        addrB[np] + dt);
            LDSM_X2(bb[6][0], bb[6][1], addrB[3] + dt);

            #pragma unroll
            for (int mt = 0; mt < 2; ++mt)
                #pragma unroll
                for (int nt = 0; nt < 7; ++nt) {
                    MMA_F16(d[mt][nt], awh[mt], bb[nt]);
                    MMA_F16(d[mt][nt], awl[mt], bb[nt]);
                }
            ++stage;
        }
        __syncthreads();   // all LDSM of this chunk done before slab_t rewrite
    }

    // ---- epilogue: direct STG.64 (px pairs never cross 28-col boundary) ----
    #pragma unroll
    for (int mt = 0; mt < 2; ++mt) {
        int obase = o0 + wm * 32 + mt * 16 + (lane >> 2);
        #pragma unroll
        for (int nt = 0; nt < 7; ++nt) {
            int px = wn * 56 + nt * 8 + (lane & 3) * 2;
            int rl = px / 28, c = px - rl * 28;
            float2* p0 = (float2*)(out + (((size_t)(b * 256 + obase)) * 28 + r0 + rl) * 28 + c);
            float2* p1 = (float2*)(out + (((size_t)(b * 256 + obase + 8)) * 28 + r0 + rl) * 28 + c);
            *p0 = make_float2(d[mt][nt][0], d[mt][nt][1]);
            *p1 = make_float2(d[mt][nt][2], d[mt][nt][3]);
        }
    }
}

// ---------------------------------------------------------------------------
extern "C" void kernel_launch(void* const* d_in, const int* in_sizes, int n_in,
                              void* d_out, int out_size) {
    const float* x     = (const float*)d_in[0];   // [32,256,28,28]
    const float* fc1_w = (const float*)d_in[1];   // [64,256]
    const float* fc2_w = (const float*)d_in[2];   // [1024,64]
    const float* fc2_b = (const float*)d_in[3];   // [1024]
    const float* wexp  = (const float*)d_in[4];   // [4,256,256,3,3]
    float* out = (float*)d_out;                   // [32,256,28,28]

    pool_kernel<<<B_ * CIN_ / 8, 256>>>(x);
    routing_kernel<<<B_, 256>>>(fc1_w, fc2_w, fc2_b);
    aggw_split_kernel<<<dim3(COUT_, 2), 256>>>(wexp);
    conv_mma_kernel<<<dim3(7, 2, B_), 256>>>(x, out);
}